// round 1
// baseline (speedup 1.0000x reference)
#include <cuda_runtime.h>
#include <math.h>

// Problem constants
constexpr int BATCH = 2;
constexpr int H     = 16;
constexpr int L     = 2048;   // LQ == LK
constexpr int D     = 64;     // d_k == d_v
constexpr int C     = 1024;   // k_dim == v_dim == n_head*d_k
constexpr long Y_ELEMS = (long)BATCH * L * C;          // 4194304
constexpr float QK_SCALE = 0.022097086912079608f;      // 1/sqrt(2048)

// GEMM tiling
#define BM 128
#define BN 64
#define BK 16

// Scratch (static device memory; no allocations allowed)
__device__ float g_qh[(long)BATCH * H * L * D];
__device__ float g_kh[(long)BATCH * H * L * D];
__device__ float g_vh[(long)BATCH * H * L * D];
__device__ float g_yh[(long)BATCH * L * H * D];
__device__ float g_Z[BATCH * H * L];
__device__ float g_invZ[BATCH * H * L];

// ---- packed f32x2 helpers (Blackwell FFMA2 path) ----
__device__ __forceinline__ unsigned long long pack2(float lo, float hi) {
    unsigned long long r;
    asm("mov.b64 %0, {%1, %2};" : "=l"(r) : "f"(lo), "f"(hi));
    return r;
}
__device__ __forceinline__ void unpack2(unsigned long long v, float& lo, float& hi) {
    asm("mov.b64 {%0, %1}, %2;" : "=f"(lo), "=f"(hi) : "l"(v));
}
__device__ __forceinline__ void fma2(unsigned long long& d, unsigned long long a, unsigned long long b) {
    asm("fma.rn.f32x2 %0, %1, %2, %0;" : "+l"(d) : "l"(a), "l"(b));
}

// ---- shared GEMM mainloop ----
// C_tile[128x64] += A[BMxK] * B, accumulators packed as row-pairs.
// B_KN = false: B is [N, K] row-major (TN gemm, dot of contiguous rows)
// B_KN = true : B is [K, N] row-major (NN gemm)
// acc[p][j]: rows (ty*8 + 2p, +1), col tx*4 + j
template<bool B_KN>
__device__ __forceinline__ void mainloop(const float* __restrict__ A, int lda,
                                         const float* __restrict__ Bp, int ldb,
                                         int K, unsigned long long acc[4][4]) {
    __shared__ float As[BK][BM + 2];
    __shared__ float Bs[BK][BN + 2];
    const int tid = threadIdx.x;
    const int tx = tid & 15, ty = tid >> 4;

    for (int k0 = 0; k0 < K; k0 += BK) {
        // Load A tile 128x16 (512 float4s, 2 per thread), store transposed
        #pragma unroll
        for (int i = 0; i < 2; i++) {
            int fi = tid + i * 256;
            int r = fi >> 2, c = (fi & 3) << 2;
            float4 v = *(const float4*)(A + (long)r * lda + k0 + c);
            As[c + 0][r] = v.x; As[c + 1][r] = v.y;
            As[c + 2][r] = v.z; As[c + 3][r] = v.w;
        }
        // Load B tile
        if (B_KN) {
            int kk = tid >> 4, c = (tid & 15) << 2;
            float4 v = *(const float4*)(Bp + (long)(k0 + kk) * ldb + c);
            Bs[kk][c + 0] = v.x; Bs[kk][c + 1] = v.y;
            Bs[kk][c + 2] = v.z; Bs[kk][c + 3] = v.w;
        } else {
            int r = tid >> 2, c = (tid & 3) << 2;
            float4 v = *(const float4*)(Bp + (long)r * ldb + k0 + c);
            Bs[c + 0][r] = v.x; Bs[c + 1][r] = v.y;
            Bs[c + 2][r] = v.z; Bs[c + 3][r] = v.w;
        }
        __syncthreads();

        #pragma unroll
        for (int k = 0; k < BK; k++) {
            unsigned long long ap[4], bd[4];
            #pragma unroll
            for (int p = 0; p < 4; p++)
                ap[p] = *(const unsigned long long*)&As[k][ty * 8 + 2 * p];
            #pragma unroll
            for (int j = 0; j < 4; j++) {
                float bv = Bs[k][tx * 4 + j];
                bd[j] = pack2(bv, bv);
            }
            #pragma unroll
            for (int p = 0; p < 4; p++)
                #pragma unroll
                for (int j = 0; j < 4; j++)
                    fma2(acc[p][j], ap[p], bd[j]);
        }
        __syncthreads();
    }
}

// ---- projection: OUT[b,h,l,d] = sum_c X[b,l,c] * W[h*64+d, c] ----
// which: 0 -> g_qh, 1 -> g_kh, 2 -> g_vh
__global__ void __launch_bounds__(256) proj_kernel(const float* __restrict__ X,
                                                   const float* __restrict__ W,
                                                   int which) {
    float* OUT = (which == 0) ? g_qh : (which == 1) ? g_kh : g_vh;
    unsigned long long acc[4][4] = {};
    const int m0 = blockIdx.y * BM;
    const int n0 = blockIdx.x * BN;
    mainloop<false>(X + (long)m0 * C, C, W + (long)n0 * C, C, C, acc);

    const int tx = threadIdx.x & 15, ty = threadIdx.x >> 4;
    const int h = blockIdx.x;  // BN == D, tiles aligned to heads
    #pragma unroll
    for (int p = 0; p < 4; p++) {
        float lo[4], hi[4];
        #pragma unroll
        for (int j = 0; j < 4; j++) unpack2(acc[p][j], lo[j], hi[j]);
        int m = m0 + ty * 8 + 2 * p;
        int b0 = m >> 11, l0 = m & 2047;
        int b1 = (m + 1) >> 11, l1 = (m + 1) & 2047;
        float4 v0 = make_float4(lo[0], lo[1], lo[2], lo[3]);
        float4 v1 = make_float4(hi[0], hi[1], hi[2], hi[3]);
        *(float4*)(OUT + ((long)(b0 * H + h) * L + l0) * D + tx * 4) = v0;
        *(float4*)(OUT + ((long)(b1 * H + h) * L + l1) * D + tx * 4) = v1;
    }
}

// ---- QK^T, scale, exp, write unnormalized attn, accumulate row sums ----
__global__ void __launch_bounds__(256) qk_kernel(float* __restrict__ attnU) {
    const int bh = blockIdx.z;
    const int m0 = blockIdx.y * BM;
    const int n0 = blockIdx.x * BN;
    const float* A  = g_qh + (long)bh * L * D + (long)m0 * D;
    const float* Bp = g_kh + (long)bh * L * D + (long)n0 * D;
    unsigned long long acc[4][4] = {};
    mainloop<false>(A, D, Bp, D, D, acc);

    __shared__ float rs[BM];
    const int tid = threadIdx.x;
    const int tx = tid & 15, ty = tid >> 4;
    if (tid < BM) rs[tid] = 0.0f;
    __syncthreads();

    float* outbase = attnU + (long)bh * L * L;
    #pragma unroll
    for (int p = 0; p < 4; p++) {
        float lo[4], hi[4];
        #pragma unroll
        for (int j = 0; j < 4; j++) unpack2(acc[p][j], lo[j], hi[j]);
        float elo[4], ehi[4], slo = 0.0f, shi = 0.0f;
        #pragma unroll
        for (int j = 0; j < 4; j++) {
            elo[j] = __expf(lo[j] * QK_SCALE); slo += elo[j];
            ehi[j] = __expf(hi[j] * QK_SCALE); shi += ehi[j];
        }
        int m = m0 + ty * 8 + 2 * p;
        *(float4*)(outbase + (long)m * L + n0 + tx * 4)       = make_float4(elo[0], elo[1], elo[2], elo[3]);
        *(float4*)(outbase + (long)(m + 1) * L + n0 + tx * 4) = make_float4(ehi[0], ehi[1], ehi[2], ehi[3]);
        atomicAdd(&rs[ty * 8 + 2 * p],     slo);
        atomicAdd(&rs[ty * 8 + 2 * p + 1], shi);
    }
    __syncthreads();
    if (tid < BM) atomicAdd(&g_Z[bh * L + m0 + tid], rs[tid]);
}

// ---- P @ V (attn already normalized in place), write yh in [b, l, h*D+d] layout ----
__global__ void __launch_bounds__(256) pv_kernel(const float* __restrict__ attnN) {
    const int bh = blockIdx.z;
    const int m0 = blockIdx.y * BM;
    const float* A  = attnN + (long)bh * L * L + (long)m0 * L;
    const float* Bp = g_vh + (long)bh * L * D;
    unsigned long long acc[4][4] = {};
    mainloop<true>(A, L, Bp, D, L, acc);

    const int tx = threadIdx.x & 15, ty = threadIdx.x >> 4;
    const int b = bh >> 4, h = bh & 15;
    #pragma unroll
    for (int p = 0; p < 4; p++) {
        float lo[4], hi[4];
        #pragma unroll
        for (int j = 0; j < 4; j++) unpack2(acc[p][j], lo[j], hi[j]);
        int m = m0 + ty * 8 + 2 * p;
        *(float4*)(g_yh + ((long)(b * L + m) * C)     + h * D + tx * 4) = make_float4(lo[0], lo[1], lo[2], lo[3]);
        *(float4*)(g_yh + ((long)(b * L + m + 1) * C) + h * D + tx * 4) = make_float4(hi[0], hi[1], hi[2], hi[3]);
    }
}

// ---- y = yh @ fc_y^T ----
__global__ void __launch_bounds__(256) final_kernel(const float* __restrict__ Wf,
                                                    float* __restrict__ Y) {
    unsigned long long acc[4][4] = {};
    const int m0 = blockIdx.y * BM;
    const int n0 = blockIdx.x * BN;
    mainloop<false>(g_yh + (long)m0 * C, C, Wf + (long)n0 * C, C, C, acc);

    const int tx = threadIdx.x & 15, ty = threadIdx.x >> 4;
    #pragma unroll
    for (int p = 0; p < 4; p++) {
        float lo[4], hi[4];
        #pragma unroll
        for (int j = 0; j < 4; j++) unpack2(acc[p][j], lo[j], hi[j]);
        int m = m0 + ty * 8 + 2 * p;
        *(float4*)(Y + (long)m * C + n0 + tx * 4)       = make_float4(lo[0], lo[1], lo[2], lo[3]);
        *(float4*)(Y + (long)(m + 1) * C + n0 + tx * 4) = make_float4(hi[0], hi[1], hi[2], hi[3]);
    }
}

// ---- tiny utility kernels ----
__global__ void zero_z_kernel() {
    int i = blockIdx.x * 256 + threadIdx.x;
    g_Z[i] = 0.0f;
}
__global__ void recip_z_kernel() {
    int i = blockIdx.x * 256 + threadIdx.x;
    g_invZ[i] = 1.0f / g_Z[i];
}
// normalize attn in place (float4 granularity; 4 consecutive cols share row)
__global__ void norm_kernel(float* __restrict__ attn) {
    long i = (long)blockIdx.x * 256 + threadIdx.x;
    float s = g_invZ[i >> 9];   // element row = (4*i) / 2048 = i >> 9
    float4* p = (float4*)attn;
    float4 v = p[i];
    v.x *= s; v.y *= s; v.z *= s; v.w *= s;
    p[i] = v;
}

extern "C" void kernel_launch(void* const* d_in, const int* in_sizes, int n_in,
                              void* d_out, int out_size) {
    const float* q    = (const float*)d_in[0];
    const float* k    = (const float*)d_in[1];
    const float* v    = (const float*)d_in[2];
    const float* w_q  = (const float*)d_in[3];
    const float* w_k  = (const float*)d_in[4];
    const float* w_v  = (const float*)d_in[5];
    const float* fc_y = (const float*)d_in[6];

    float* y    = (float*)d_out;            // (B, LQ, V_DIM) = 4194304 floats
    float* attn = (float*)d_out + Y_ELEMS;  // (B, H, LQ, LK) = 134217728 floats

    // 1. zero softmax denominators (re-done every graph replay)
    zero_z_kernel<<<(BATCH * H * L) / 256, 256>>>();

    // 2. projections -> head-major scratch [b,h,l,d]
    dim3 gproj(C / BN, (BATCH * L) / BM);
    proj_kernel<<<gproj, 256>>>(q, w_q, 0);
    proj_kernel<<<gproj, 256>>>(k, w_k, 1);
    proj_kernel<<<gproj, 256>>>(v, w_v, 2);

    // 3. S = QK^T / sqrt(LK); attn_unnorm = exp(S); Z[row] += rowsum
    dim3 gqk(L / BN, L / BM, BATCH * H);
    qk_kernel<<<gqk, 256>>>(attn);

    // 4. invZ, then normalize attn in place (this IS the softmax output)
    recip_z_kernel<<<(BATCH * H * L) / 256, 256>>>();
    long n4 = (long)BATCH * H * L * L / 4;
    norm_kernel<<<(unsigned)(n4 / 256), 256>>>(attn);

    // 5. yh = attn @ V, written as [b, l, h*D+d]
    dim3 gpv(1, L / BM, BATCH * H);
    pv_kernel<<<gpv, 256>>>(attn);

    // 6. y = yh @ fc_y^T
    dim3 gfin(C / BN, (BATCH * L) / BM);
    final_kernel<<<gfin, 256>>>(fc_y, y);
}

// round 3
// speedup vs baseline: 2.6002x; 2.6002x over previous
#include <cuda_runtime.h>
#include <cstdint>
#include <math.h>

// ---------------- problem constants ----------------
constexpr int BATCH = 2;
constexpr int H     = 16;
constexpr int L     = 2048;
constexpr int D     = 64;
constexpr int C     = 1024;
constexpr long Y_ELEMS = (long)BATCH * L * C;
constexpr float QK_SCALE = 0.022097086912079608f;   // 1/sqrt(2048)

// GEMM tiling
#define BM 128
#define BN 64
#define BK 32
#define SST 36          // smem row stride in floats (BK+4: conflict-free frags)

// ---------------- scratch ----------------
__device__ float g_qh[(long)BATCH * H * L * D];   // [bh][l][d]
__device__ float g_kh[(long)BATCH * H * L * D];   // [bh][l][d]
__device__ float g_vt[(long)BATCH * H * D * L];   // [bh][d][l]  (V transposed)
__device__ float g_yh[(long)BATCH * L * H * D];   // [b][l][h*64+d]
__device__ float g_Z[BATCH * H * L];
__device__ float g_invZ[BATCH * H * L];

// ---------------- helpers ----------------
__device__ __forceinline__ uint32_t f2tf(float f) {
    uint32_t r;
    asm("cvt.rna.tf32.f32 %0, %1;" : "=r"(r) : "f"(f));
    return r;
}
__device__ __forceinline__ void mma8(float* c, const uint32_t* a, const uint32_t* b) {
    asm volatile("mma.sync.aligned.m16n8k8.row.col.f32.tf32.tf32.f32 "
        "{%0,%1,%2,%3}, {%4,%5,%6,%7}, {%8,%9}, {%0,%1,%2,%3};"
        : "+f"(c[0]), "+f"(c[1]), "+f"(c[2]), "+f"(c[3])
        : "r"(a[0]), "r"(a[1]), "r"(a[2]), "r"(a[3]), "r"(b[0]), "r"(b[1]));
}

// ---------------- generic TN-GEMM core ----------------
// D[128x64] = A[128xK] * B[64xK]^T, fp32 gmem (K contiguous), tf32 MMA.
// acc[mt][nt][4]: warp (wm,wn); row = wm+mt*16+group(+8), col = wn+nt*8+tig*2(+1)
// WB: after each A chunk is consumed, scale by invz[row] and write back to
// wb_out (fused softmax normalization for the PV kernel).
template<bool WB>
__device__ __forceinline__ void gemm_core(const float* __restrict__ A, long lda,
                                          const float* __restrict__ Bp, long ldb,
                                          int niter, float acc[2][4][4],
                                          uint32_t* As, uint32_t* Bs,
                                          float* wb_out, long wb_ld,
                                          const float* invz) {
    const int tid = threadIdx.x;
    const int r8 = tid >> 3, c8 = tid & 7;
    const int lane = tid & 31, wid = tid >> 5;
    const int wm = (wid & 3) * 32, wn = (wid >> 2) * 32;
    const int group = lane >> 2, tig = lane & 3;

    for (int it = 0; it < niter; it++) {
        const long k0 = (long)it * BK;
        float4 av[4], bv[2];
        #pragma unroll
        for (int i = 0; i < 4; i++)
            av[i] = *(const float4*)(A + (long)(r8 + i * 32) * lda + k0 + c8 * 4);
        #pragma unroll
        for (int i = 0; i < 2; i++)
            bv[i] = *(const float4*)(Bp + (long)(r8 + i * 32) * ldb + k0 + c8 * 4);

        __syncthreads();   // previous tile fully consumed (incl. WB)
        #pragma unroll
        for (int i = 0; i < 4; i++)
            *(uint4*)&As[(r8 + i * 32) * SST + c8 * 4] =
                make_uint4(f2tf(av[i].x), f2tf(av[i].y), f2tf(av[i].z), f2tf(av[i].w));
        #pragma unroll
        for (int i = 0; i < 2; i++)
            *(uint4*)&Bs[(r8 + i * 32) * SST + c8 * 4] =
                make_uint4(f2tf(bv[i].x), f2tf(bv[i].y), f2tf(bv[i].z), f2tf(bv[i].w));
        __syncthreads();

        #pragma unroll
        for (int ks = 0; ks < 4; ks++) {
            const int kk = ks * 8;
            uint32_t af[2][4], bf[4][2];
            #pragma unroll
            for (int mt = 0; mt < 2; mt++) {
                const int base = (wm + mt * 16 + group) * SST + kk + tig;
                af[mt][0] = As[base];
                af[mt][1] = As[base + 8 * SST];
                af[mt][2] = As[base + 4];
                af[mt][3] = As[base + 8 * SST + 4];
            }
            #pragma unroll
            for (int nt = 0; nt < 4; nt++) {
                const int nb = (wn + nt * 8 + group) * SST + kk + tig;
                bf[nt][0] = Bs[nb];
                bf[nt][1] = Bs[nb + 4];
            }
            #pragma unroll
            for (int mt = 0; mt < 2; mt++)
                #pragma unroll
                for (int nt = 0; nt < 4; nt++)
                    mma8(acc[mt][nt], af[mt], bf[nt]);
        }

        if (WB) {
            #pragma unroll
            for (int i = 0; i < 4; i++) {
                const int r = r8 + i * 32;
                const uint32_t* p = &As[r * SST + c8 * 4];
                const float s = invz[r];
                *(float4*)(wb_out + (long)r * wb_ld + k0 + c8 * 4) =
                    make_float4(__uint_as_float(p[0]) * s, __uint_as_float(p[1]) * s,
                                __uint_as_float(p[2]) * s, __uint_as_float(p[3]) * s);
            }
        }
    }
}

// ---------------- kernels ----------------
// projection: OUT = X[BL x C] @ W[h-block]^T.  which: 0->qh, 1->kh, 2->vt (transposed)
__global__ void __launch_bounds__(256) proj_kernel(const float* __restrict__ X,
                                                   const float* __restrict__ W, int which) {
    __shared__ uint32_t As[BM * SST], Bs[BN * SST];
    float acc[2][4][4] = {};
    const int m0 = blockIdx.y * BM, h = blockIdx.x;
    gemm_core<false>(X + (long)m0 * C, C, W + (long)h * 64 * C, C, C / BK, acc,
                     As, Bs, nullptr, 0, nullptr);

    const int lane = threadIdx.x & 31, wid = threadIdx.x >> 5;
    const int wm = (wid & 3) * 32, wn = (wid >> 2) * 32;
    const int group = lane >> 2, tig = lane & 3;
    if (which == 2) {
        float* out = nullptr;  // per-element addressing below
        #pragma unroll
        for (int mt = 0; mt < 2; mt++)
            #pragma unroll
            for (int half = 0; half < 2; half++) {
                const int m = m0 + wm + mt * 16 + group + 8 * half;
                const int b = m >> 11, l = m & 2047;
                out = g_vt + (long)(b * H + h) * D * L;
                #pragma unroll
                for (int nt = 0; nt < 4; nt++) {
                    const int d0 = wn + nt * 8 + tig * 2;
                    out[(long)d0 * L + l]       = acc[mt][nt][2 * half];
                    out[(long)(d0 + 1) * L + l] = acc[mt][nt][2 * half + 1];
                }
            }
    } else {
        float* base = (which == 0 ? g_qh : g_kh);
        #pragma unroll
        for (int mt = 0; mt < 2; mt++)
            #pragma unroll
            for (int half = 0; half < 2; half++) {
                const int m = m0 + wm + mt * 16 + group + 8 * half;
                const int b = m >> 11, l = m & 2047;
                float* out = base + ((long)(b * H + h) * L + l) * D;
                #pragma unroll
                for (int nt = 0; nt < 4; nt++)
                    *(float2*)(out + wn + nt * 8 + tig * 2) =
                        make_float2(acc[mt][nt][2 * half], acc[mt][nt][2 * half + 1]);
            }
    }
}

// QK^T -> exp -> unnormalized attn + row-sum atomics
__global__ void __launch_bounds__(256) qk_kernel(float* __restrict__ attnU) {
    __shared__ uint32_t As[BM * SST], Bs[BN * SST];
    float acc[2][4][4] = {};
    const int n0 = blockIdx.x * BN, m0 = blockIdx.y * BM, bh = blockIdx.z;
    gemm_core<false>(g_qh + ((long)bh * L + m0) * D, D,
                     g_kh + ((long)bh * L + n0) * D, D, D / BK, acc,
                     As, Bs, nullptr, 0, nullptr);

    const int lane = threadIdx.x & 31, wid = threadIdx.x >> 5;
    const int wm = (wid & 3) * 32, wn = (wid >> 2) * 32;
    const int group = lane >> 2, tig = lane & 3;
    float* outbase = attnU + (long)bh * L * L;
    #pragma unroll
    for (int mt = 0; mt < 2; mt++)
        #pragma unroll
        for (int half = 0; half < 2; half++) {
            const int row = m0 + wm + mt * 16 + group + 8 * half;
            float sum = 0.0f;
            float e[4][2];
            #pragma unroll
            for (int nt = 0; nt < 4; nt++) {
                e[nt][0] = __expf(acc[mt][nt][2 * half] * QK_SCALE);
                e[nt][1] = __expf(acc[mt][nt][2 * half + 1] * QK_SCALE);
                sum += e[nt][0] + e[nt][1];
            }
            float* outr = outbase + (long)row * L + n0;
            #pragma unroll
            for (int nt = 0; nt < 4; nt++)
                *(float2*)(outr + wn + nt * 8 + tig * 2) = make_float2(e[nt][0], e[nt][1]);
            // reduce over the 4 lanes (tig) sharing this row
            sum += __shfl_xor_sync(0xFFFFFFFF, sum, 1);
            sum += __shfl_xor_sync(0xFFFFFFFF, sum, 2);
            if (tig == 0) atomicAdd(&g_Z[bh * L + row], sum);
        }
}

// PV with fused normalization: reads unnormalized attn, writes normalized attn + yh
__global__ void __launch_bounds__(256) pv_kernel(float* __restrict__ attn) {
    __shared__ uint32_t As[BM * SST], Bs[BN * SST];
    __shared__ float invz_s[BM];
    const int m0 = blockIdx.x * BM, bh = blockIdx.y;
    if (threadIdx.x < BM) invz_s[threadIdx.x] = g_invZ[bh * L + m0 + threadIdx.x];

    float acc[2][4][4] = {};
    float* arow = attn + (long)bh * L * L + (long)m0 * L;
    gemm_core<true>(arow, L, g_vt + (long)bh * D * L, L, L / BK, acc,
                    As, Bs, arow, L, invz_s);

    const int lane = threadIdx.x & 31, wid = threadIdx.x >> 5;
    const int wm = (wid & 3) * 32, wn = (wid >> 2) * 32;
    const int group = lane >> 2, tig = lane & 3;
    const int b = bh >> 4, hh = bh & 15;
    #pragma unroll
    for (int mt = 0; mt < 2; mt++)
        #pragma unroll
        for (int half = 0; half < 2; half++) {
            const int r = wm + mt * 16 + group + 8 * half;
            const float s = invz_s[r];
            float* out = g_yh + (long)(b * L + m0 + r) * C + hh * 64;
            #pragma unroll
            for (int nt = 0; nt < 4; nt++)
                *(float2*)(out + wn + nt * 8 + tig * 2) =
                    make_float2(acc[mt][nt][2 * half] * s, acc[mt][nt][2 * half + 1] * s);
        }
}

// y = yh @ fc_y^T
__global__ void __launch_bounds__(256) final_kernel(const float* __restrict__ Wf,
                                                    float* __restrict__ Y) {
    __shared__ uint32_t As[BM * SST], Bs[BN * SST];
    float acc[2][4][4] = {};
    const int n0 = blockIdx.x * BN, m0 = blockIdx.y * BM;
    gemm_core<false>(g_yh + (long)m0 * C, C, Wf + (long)n0 * C, C, C / BK, acc,
                     As, Bs, nullptr, 0, nullptr);

    const int lane = threadIdx.x & 31, wid = threadIdx.x >> 5;
    const int wm = (wid & 3) * 32, wn = (wid >> 2) * 32;
    const int group = lane >> 2, tig = lane & 3;
    #pragma unroll
    for (int mt = 0; mt < 2; mt++)
        #pragma unroll
        for (int half = 0; half < 2; half++) {
            const int row = m0 + wm + mt * 16 + group + 8 * half;
            float* out = Y + (long)row * C + n0;
            #pragma unroll
            for (int nt = 0; nt < 4; nt++)
                *(float2*)(out + wn + nt * 8 + tig * 2) =
                    make_float2(acc[mt][nt][2 * half], acc[mt][nt][2 * half + 1]);
        }
}

__global__ void zero_z_kernel() { g_Z[blockIdx.x * 256 + threadIdx.x] = 0.0f; }
__global__ void recip_z_kernel() {
    int i = blockIdx.x * 256 + threadIdx.x;
    g_invZ[i] = 1.0f / g_Z[i];
}

extern "C" void kernel_launch(void* const* d_in, const int* in_sizes, int n_in,
                              void* d_out, int out_size) {
    const float* q    = (const float*)d_in[0];
    const float* k    = (const float*)d_in[1];
    const float* v    = (const float*)d_in[2];
    const float* w_q  = (const float*)d_in[3];
    const float* w_k  = (const float*)d_in[4];
    const float* w_v  = (const float*)d_in[5];
    const float* fc_y = (const float*)d_in[6];

    float* y    = (float*)d_out;
    float* attn = (float*)d_out + Y_ELEMS;

    zero_z_kernel<<<(BATCH * H * L) / 256, 256>>>();

    dim3 gproj(16, 32);                       // (head, m-tile)
    proj_kernel<<<gproj, 256>>>(q, w_q, 0);
    proj_kernel<<<gproj, 256>>>(k, w_k, 1);
    proj_kernel<<<gproj, 256>>>(v, w_v, 2);

    dim3 gqk(32, 16, 32);                     // (n-tile, m-tile, bh)
    qk_kernel<<<gqk, 256>>>(attn);

    recip_z_kernel<<<(BATCH * H * L) / 256, 256>>>();

    dim3 gpv(16, 32);                         // (m-tile, bh)
    pv_kernel<<<gpv, 256>>>(attn);

    dim3 gfin(16, 32);                        // (n-tile, m-tile)
    final_kernel<<<gfin, 256>>>(fc_y, y);
}

// round 5
// speedup vs baseline: 2.9928x; 1.1510x over previous
#include <cuda_runtime.h>
#include <cstdint>
#include <math.h>

// ---------------- problem constants ----------------
constexpr int BATCH = 2;
constexpr int H     = 16;
constexpr int L     = 2048;
constexpr int D     = 64;
constexpr int C     = 1024;
constexpr long Y_ELEMS = (long)BATCH * L * C;
constexpr float QK_SCALE = 0.022097086912079608f;   // 1/sqrt(2048)

#define SST 36   // smem row stride (floats): 16B-aligned rows (144B), conflict-free

// ---------------- scratch ----------------
__device__ float g_qh[(long)BATCH * H * L * D];   // [bh][l][d]
__device__ float g_kh[(long)BATCH * H * L * D];   // [bh][l][d]
__device__ float g_vt[(long)BATCH * H * D * L];   // [bh][d][l]  (V transposed)
__device__ float g_yh[(long)BATCH * L * H * D];   // [b][l][h*64+d]
__device__ float g_Z[BATCH * H * L];
__device__ float g_invZ[BATCH * H * L];

// ---------------- helpers ----------------
__device__ __forceinline__ uint32_t f2tf(float f) {
    uint32_t r;
    asm("cvt.rna.tf32.f32 %0, %1;" : "=r"(r) : "f"(f));
    return r;
}
__device__ __forceinline__ void mma8(float* c, const uint32_t* a, const uint32_t* b) {
    asm volatile("mma.sync.aligned.m16n8k8.row.col.f32.tf32.tf32.f32 "
        "{%0,%1,%2,%3}, {%4,%5,%6,%7}, {%8,%9}, {%0,%1,%2,%3};"
        : "+f"(c[0]), "+f"(c[1]), "+f"(c[2]), "+f"(c[3])
        : "r"(a[0]), "r"(a[1]), "r"(a[2]), "r"(a[3]), "r"(b[0]), "r"(b[1]));
}

// ---------------- GEMM core v3: 128 threads, 4 warps, warp tile 64x64 ----------------
// D[BM_ x BN_] = A[BM_ x K] * B[BN_ x K]^T, fp32 gmem (K contiguous), tf32 MMA.
// Warp grid: WM_ warps along M, 4/WM_ along N. BK=32 per iteration, single-buffered
// static smem, register-staged loads with tf32 conversion on the smem-store path.
// acc[mt][nt][4]: row = wm + mt*16 + group (+8), col = wn + nt*8 + tig*2 (+1).
// WB: after compute, scale the consumed A chunk by invz[row] and write to wb_out
// (fused softmax normalization for the PV kernel).
template<int BM_, int BN_, int WM_, bool WB>
__device__ __forceinline__ void gemm3(const float* __restrict__ A, long lda,
                                      const float* __restrict__ Bp, long ldb,
                                      int niter, float acc[4][8][4],
                                      uint32_t* __restrict__ As, uint32_t* __restrict__ Bs,
                                      float* __restrict__ wb_out, long wb_ld,
                                      const float* __restrict__ invz) {
    constexpr int NA = BM_ / 16, NB = BN_ / 16;   // float4 per thread (128 threads)
    const int tid = threadIdx.x;
    const int lane = tid & 31, wid = tid >> 5, group = lane >> 2, tig = lane & 3;
    const int wm = (wid % WM_) * 64, wn = (wid / WM_) * 64;

    for (int it = 0; it < niter; it++) {
        const long k0 = (long)it * 32;
        float4 av[NA], bv[NB];
        #pragma unroll
        for (int i = 0; i < NA; i++) {
            int c = tid + i * 128, r = c >> 3, q = (c & 7) * 4;
            av[i] = *(const float4*)(A + (long)r * lda + k0 + q);
        }
        #pragma unroll
        for (int i = 0; i < NB; i++) {
            int c = tid + i * 128, r = c >> 3, q = (c & 7) * 4;
            bv[i] = *(const float4*)(Bp + (long)r * ldb + k0 + q);
        }
        __syncthreads();   // previous iteration fully consumed (incl. WB)
        #pragma unroll
        for (int i = 0; i < NA; i++) {
            int c = tid + i * 128, r = c >> 3, q = (c & 7) * 4;
            *(uint4*)&As[r * SST + q] =
                make_uint4(f2tf(av[i].x), f2tf(av[i].y), f2tf(av[i].z), f2tf(av[i].w));
        }
        #pragma unroll
        for (int i = 0; i < NB; i++) {
            int c = tid + i * 128, r = c >> 3, q = (c & 7) * 4;
            *(uint4*)&Bs[r * SST + q] =
                make_uint4(f2tf(bv[i].x), f2tf(bv[i].y), f2tf(bv[i].z), f2tf(bv[i].w));
        }
        __syncthreads();

        #pragma unroll
        for (int ks = 0; ks < 4; ks++) {
            const int kk = ks * 8;
            uint32_t af[4][4], bf[8][2];
            #pragma unroll
            for (int mt = 0; mt < 4; mt++) {
                const int ba = (wm + mt * 16 + group) * SST + kk + tig;
                af[mt][0] = As[ba];
                af[mt][1] = As[ba + 8 * SST];
                af[mt][2] = As[ba + 4];
                af[mt][3] = As[ba + 8 * SST + 4];
            }
            #pragma unroll
            for (int nt = 0; nt < 8; nt++) {
                const int bb = (wn + nt * 8 + group) * SST + kk + tig;
                bf[nt][0] = Bs[bb];
                bf[nt][1] = Bs[bb + 4];
            }
            #pragma unroll
            for (int mt = 0; mt < 4; mt++)
                #pragma unroll
                for (int nt = 0; nt < 8; nt++)
                    mma8(acc[mt][nt], af[mt], bf[nt]);
        }

        if (WB) {   // next iteration's stores wait at its first __syncthreads
            #pragma unroll
            for (int i = 0; i < NA; i++) {
                int c = tid + i * 128, r = c >> 3, q = (c & 7) * 4;
                const uint32_t* p = &As[r * SST + q];
                const float s = invz[r];
                *(float4*)(wb_out + (long)r * wb_ld + k0 + q) =
                    make_float4(__uint_as_float(p[0]) * s, __uint_as_float(p[1]) * s,
                                __uint_as_float(p[2]) * s, __uint_as_float(p[3]) * s);
            }
        }
    }
}

// ---------------- kernels ----------------
// projection: OUT = X[BL x C] @ W^T.  which: 0->qh, 1->kh, 2->vt (transposed)
__global__ void __launch_bounds__(128) proj_kernel(const float* __restrict__ X,
                                                   const float* __restrict__ W, int which) {
    __shared__ uint32_t As[128 * SST], Bs[128 * SST];
    float acc[4][8][4] = {};
    const int m0 = blockIdx.y * 128, n0 = blockIdx.x * 128;
    gemm3<128, 128, 2, false>(X + (long)m0 * C, C, W + (long)n0 * C, C, C / 32, acc,
                              As, Bs, nullptr, 0, nullptr);

    const int lane = threadIdx.x & 31, wid = threadIdx.x >> 5;
    const int wm = (wid % 2) * 64, wn = (wid / 2) * 64;
    const int group = lane >> 2, tig = lane & 3;
    #pragma unroll
    for (int mt = 0; mt < 4; mt++)
        #pragma unroll
        for (int half = 0; half < 2; half++) {
            const int m = m0 + wm + mt * 16 + group + 8 * half;
            const int b = m >> 11, l = m & 2047;
            if (which == 2) {
                #pragma unroll
                for (int nt = 0; nt < 8; nt++) {
                    const int n = n0 + wn + nt * 8 + tig * 2;
                    const int h = n >> 6, d = n & 63;
                    float* out = g_vt + (long)(b * H + h) * D * L;
                    out[(long)d * L + l]       = acc[mt][nt][2 * half];
                    out[(long)(d + 1) * L + l] = acc[mt][nt][2 * half + 1];
                }
            } else {
                float* base = (which == 0) ? g_qh : g_kh;
                #pragma unroll
                for (int nt = 0; nt < 8; nt++) {
                    const int n = n0 + wn + nt * 8 + tig * 2;
                    const int h = n >> 6, d = n & 63;
                    *(float2*)(base + ((long)(b * H + h) * L + l) * D + d) =
                        make_float2(acc[mt][nt][2 * half], acc[mt][nt][2 * half + 1]);
                }
            }
        }
}

// QK^T -> exp -> unnormalized attn + row-sum atomics
__global__ void __launch_bounds__(128) qk_kernel(float* __restrict__ attnU) {
    __shared__ uint32_t As[128 * SST], Bs[128 * SST];
    float acc[4][8][4] = {};
    const int n0 = blockIdx.x * 128, m0 = blockIdx.y * 128, bh = blockIdx.z;
    gemm3<128, 128, 2, false>(g_qh + ((long)bh * L + m0) * D, D,
                              g_kh + ((long)bh * L + n0) * D, D, 2, acc,
                              As, Bs, nullptr, 0, nullptr);

    const int lane = threadIdx.x & 31, wid = threadIdx.x >> 5;
    const int wm = (wid % 2) * 64, wn = (wid / 2) * 64;
    const int group = lane >> 2, tig = lane & 3;
    float* outbase = attnU + (long)bh * L * L;
    #pragma unroll
    for (int mt = 0; mt < 4; mt++)
        #pragma unroll
        for (int half = 0; half < 2; half++) {
            const int row = m0 + wm + mt * 16 + group + 8 * half;
            float* outr = outbase + (long)row * L + n0 + wn;
            float sum = 0.0f;
            #pragma unroll
            for (int nt = 0; nt < 8; nt++) {
                float e0 = __expf(acc[mt][nt][2 * half] * QK_SCALE);
                float e1 = __expf(acc[mt][nt][2 * half + 1] * QK_SCALE);
                sum += e0 + e1;
                *(float2*)(outr + nt * 8 + tig * 2) = make_float2(e0, e1);
            }
            sum += __shfl_xor_sync(0xFFFFFFFF, sum, 1);
            sum += __shfl_xor_sync(0xFFFFFFFF, sum, 2);
            if (tig == 0) atomicAdd(&g_Z[bh * L + row], sum);
        }
}

// PV with fused normalization: reads unnormalized attn, writes normalized attn
// in place (tf32-rounded * invz) + scaled yh.
__global__ void __launch_bounds__(128) pv_kernel(float* __restrict__ attn) {
    __shared__ uint32_t As[256 * SST], Bs[64 * SST];
    __shared__ float invz_s[256];
    const int m0 = blockIdx.x * 256, bh = blockIdx.y;
    for (int i = threadIdx.x; i < 256; i += 128)
        invz_s[i] = g_invZ[bh * L + m0 + i];
    __syncthreads();

    float acc[4][8][4] = {};
    float* arow = attn + (long)bh * L * L + (long)m0 * L;
    gemm3<256, 64, 4, true>(arow, L, g_vt + (long)bh * D * L, L, L / 32, acc,
                            As, Bs, arow, L, invz_s);

    const int lane = threadIdx.x & 31, wid = threadIdx.x >> 5;
    const int wm = wid * 64;
    const int group = lane >> 2, tig = lane & 3;
    const int b = bh >> 4, hh = bh & 15;
    #pragma unroll
    for (int mt = 0; mt < 4; mt++)
        #pragma unroll
        for (int half = 0; half < 2; half++) {
            const int rl = wm + mt * 16 + group + 8 * half;
            const float s = invz_s[rl];
            float* out = g_yh + (long)(b * L + m0 + rl) * C + hh * 64;
            #pragma unroll
            for (int nt = 0; nt < 8; nt++)
                *(float2*)(out + nt * 8 + tig * 2) =
                    make_float2(acc[mt][nt][2 * half] * s, acc[mt][nt][2 * half + 1] * s);
        }
}

// y = yh @ fc_y^T
__global__ void __launch_bounds__(128) final_kernel(const float* __restrict__ Wf,
                                                    float* __restrict__ Y) {
    __shared__ uint32_t As[128 * SST], Bs[128 * SST];
    float acc[4][8][4] = {};
    const int n0 = blockIdx.x * 128, m0 = blockIdx.y * 128;
    gemm3<128, 128, 2, false>(g_yh + (long)m0 * C, C, Wf + (long)n0 * C, C, C / 32, acc,
                              As, Bs, nullptr, 0, nullptr);

    const int lane = threadIdx.x & 31, wid = threadIdx.x >> 5;
    const int wm = (wid % 2) * 64, wn = (wid / 2) * 64;
    const int group = lane >> 2, tig = lane & 3;
    #pragma unroll
    for (int mt = 0; mt < 4; mt++)
        #pragma unroll
        for (int half = 0; half < 2; half++) {
            const int row = m0 + wm + mt * 16 + group + 8 * half;
            float* out = Y + (long)row * C + n0 + wn;
            #pragma unroll
            for (int nt = 0; nt < 8; nt++)
                *(float2*)(out + nt * 8 + tig * 2) =
                    make_float2(acc[mt][nt][2 * half], acc[mt][nt][2 * half + 1]);
        }
}

// ---------------- utility kernels ----------------
__global__ void zero_z_kernel() { g_Z[blockIdx.x * 256 + threadIdx.x] = 0.0f; }
__global__ void recip_z_kernel() {
    int i = blockIdx.x * 256 + threadIdx.x;
    g_invZ[i] = 1.0f / g_Z[i];
}

extern "C" void kernel_launch(void* const* d_in, const int* in_sizes, int n_in,
                              void* d_out, int out_size) {
    const float* q    = (const float*)d_in[0];
    const float* k    = (const float*)d_in[1];
    const float* v    = (const float*)d_in[2];
    const float* w_q  = (const float*)d_in[3];
    const float* w_k  = (const float*)d_in[4];
    const float* w_v  = (const float*)d_in[5];
    const float* fc_y = (const float*)d_in[6];

    float* y    = (float*)d_out;
    float* attn = (float*)d_out + Y_ELEMS;

    zero_z_kernel<<<(BATCH * H * L) / 256, 256>>>();

    // 1. projections -> head-major scratch
    dim3 gproj(8, 32);                        // (n-tile, m-tile)
    proj_kernel<<<gproj, 128>>>(q, w_q, 0);
    proj_kernel<<<gproj, 128>>>(k, w_k, 1);
    proj_kernel<<<gproj, 128>>>(v, w_v, 2);

    // 2. S = QK^T/sqrt(LK); attnU = exp(S); Z += rowsums
    dim3 gqk(16, 16, 32);                     // (n-tile, m-tile, bh)
    qk_kernel<<<gqk, 128>>>(attn);

    recip_z_kernel<<<(BATCH * H * L) / 256, 256>>>();

    // 3. yh = attn @ V with fused attn normalization writeback
    dim3 gpv(8, 32);                          // (m-tile, bh)
    pv_kernel<<<gpv, 128>>>(attn);

    // 4. y = yh @ fc_y^T
    dim3 gfin(8, 32);                         // (n-tile, m-tile)
    final_kernel<<<gfin, 128>>>(fc_y, y);
}